// round 5
// baseline (speedup 1.0000x reference)
#include <cuda_runtime.h>
#include <cuda_bf16.h>
#include <math.h>

#define BATCH   128
#define OUT_DIM 1024
#define IN_DIM  2048
#define MAXNNZ  64          // Poisson(8): P(row nnz > 64) ~ 1e-40 — safe cap
#define NSTRAIGHT 16        // unconditional gathers; sentinel-padded
#define GRID    192
#define THREADS 256

// Scratch (no allocations allowed anywhere):
__device__ int            g_cnt[OUT_DIM];
__device__ unsigned short g_idx[OUT_DIM][MAXNNZ];     // row-major, 128B rows
__device__ float          g_xT[(IN_DIM + 1) * BATCH]; // transposed x + sentinel row = 1.0f
__device__ unsigned long long g_bar;                  // monotonic grid barrier (replay-safe)

// Software grid barrier: monotonic counter, no reset needed across graph
// replays. Every launch adds exactly GRID arrivals; target derived from the
// observed generation. All GRID blocks fit in one wave -> always co-resident.
__device__ __forceinline__ void grid_sync() {
    __syncthreads();
    if (threadIdx.x == 0) {
        __threadfence();                               // release phase-1 writes
        unsigned long long old = atomicAdd(&g_bar, 1ULL);
        unsigned long long target = (old / GRID + 1ULL) * GRID;
        while (*(volatile unsigned long long*)&g_bar < target)
            __nanosleep(64);
    }
    __syncthreads();
}

__global__ void __launch_bounds__(THREADS)
bp_fused(const float* __restrict__ mask, const float* __restrict__ x,
         float* __restrict__ out) {
    __shared__ float s_t[32][33];
    const int tid  = threadIdx.x;
    const int lane = tid & 31;

    // ================= Phase 1: build indices + transpose x =================
    if (blockIdx.x < 128) {
        // ---- index build: warp = one mask row, whole 8KB row in flight ----
        const int o = blockIdx.x * 8 + (tid >> 5);
        const float4* row4 =
            reinterpret_cast<const float4*>(mask + (size_t)o * IN_DIM);

        float4 v[16];
        #pragma unroll
        for (int u = 0; u < 16; u++) v[u] = row4[u * 32 + lane];

        int mycnt = 0;
        #pragma unroll
        for (int u = 0; u < 16; u++)
            mycnt += (v[u].x != 0.0f) + (v[u].y != 0.0f) +
                     (v[u].z != 0.0f) + (v[u].w != 0.0f);

        int scan = mycnt;                              // inclusive warp scan
        #pragma unroll
        for (int d = 1; d < 32; d <<= 1) {
            int t = __shfl_up_sync(0xffffffffu, scan, d);
            if (lane >= d) scan += t;
        }
        int total = __shfl_sync(0xffffffffu, scan, 31);
        int pos   = scan - mycnt;                      // order-free is fine

        #pragma unroll
        for (int u = 0; u < 16; u++) {
            float m[4] = {v[u].x, v[u].y, v[u].z, v[u].w};
            #pragma unroll
            for (int k = 0; k < 4; k++) {
                if (m[k] != 0.0f) {
                    if (pos < MAXNNZ)
                        g_idx[o][pos] = (unsigned short)((u * 32 + lane) * 4 + k);
                    pos++;
                }
            }
        }
        for (int j = total + lane; j < NSTRAIGHT; j += 32)  // sentinel pad
            g_idx[o][j] = (unsigned short)IN_DIM;
        if (lane == 0) g_cnt[o] = total < MAXNNZ ? total : MAXNNZ;

    } else {
        // ---- transpose strip: 32 columns x 128 batches ----
        const int c0 = (blockIdx.x - 128) * 32;
        const int tx = lane;
        const int ty = tid >> 5;                       // 0..7
        #pragma unroll
        for (int bt = 0; bt < 4; bt++) {
            const int b0 = bt * 32;
            #pragma unroll
            for (int i = 0; i < 4; i++)
                s_t[ty + 8 * i][tx] =
                    x[(size_t)(b0 + ty + 8 * i) * IN_DIM + c0 + tx];
            __syncthreads();
            #pragma unroll
            for (int i = 0; i < 4; i++)
                g_xT[(size_t)(c0 + ty + 8 * i) * BATCH + b0 + tx] =
                    s_t[tx][ty + 8 * i];
            __syncthreads();
        }
        if (blockIdx.x == 128 && tid < BATCH)          // sentinel row -> 1.0f
            g_xT[(size_t)IN_DIM * BATCH + tid] = 1.0f;
    }

    // ========================== grid barrier ================================
    grid_sync();

    // ================= Phase 2: check-node update ===========================
    // Blocks [0,128): tile = 32 check nodes x 32 batches. Each warp handles
    // 4 o's x 32 batch-lanes: indices warp-uniform (broadcast), 64 independent
    // fully-coalesced gathers from L2-resident g_xT in flight.
    if (blockIdx.x < 128) {
        const int o0 = (blockIdx.x >> 2) * 32;
        const int b0 = (blockIdx.x & 3) * 32;
        const int w  = tid >> 5;

        #pragma unroll
        for (int q = 0; q < 4; q++) {
            const int ol = w * 4 + q;                  // local o: 0..31
            const int o  = o0 + ol;

            const uint4* gi = reinterpret_cast<const uint4*>(&g_idx[o][0]);
            const uint4 A = gi[0], B = gi[1];          // uniform -> broadcast
            const int   n = g_cnt[o];

            int id[NSTRAIGHT];
            {
                const unsigned wd[8] = {A.x, A.y, A.z, A.w, B.x, B.y, B.z, B.w};
                #pragma unroll
                for (int k = 0; k < 8; k++) {
                    id[2 * k]     = wd[k] & 0xffffu;
                    id[2 * k + 1] = wd[k] >> 16;
                }
            }

            float v[NSTRAIGHT];
            #pragma unroll
            for (int k = 0; k < NSTRAIGHT; k++)
                v[k] = g_xT[(size_t)id[k] * BATCH + b0 + lane];

            float p = (((v[0]  * v[1])  * (v[2]  * v[3])) *
                       ((v[4]  * v[5])  * (v[6]  * v[7]))) *
                      (((v[8]  * v[9])  * (v[10] * v[11])) *
                       ((v[12] * v[13]) * (v[14] * v[15])));

            #pragma unroll 1
            for (int j = NSTRAIGHT; j < n; j++)        // warp-uniform, rare
                p *= g_xT[(size_t)g_idx[o][j] * BATCH + b0 + lane];

            const float lim = 1.0f - 1e-7f;            // folds to 0.99999988f
            p = fminf(fmaxf(p, -lim), lim);
            s_t[ol][lane] = __logf((1.0f + p) / (1.0f - p));
        }
        __syncthreads();

        #pragma unroll
        for (int e = 0; e < 4; e++) {                  // coalesced stores
            const int idx = tid + e * 256;
            const int r = idx >> 5;                    // batch local
            const int c = idx & 31;                    // o local
            out[(size_t)(b0 + r) * OUT_DIM + o0 + c] = s_t[c][r];
        }
    }
}

// ---------------------------------------------------------------------------
extern "C" void kernel_launch(void* const* d_in, const int* in_sizes, int n_in,
                              void* d_out, int out_size) {
    const float* x    = (const float*)d_in[0];   // [128, 2048]
    const float* mask = (const float*)d_in[1];   // [1024, 2048]
    float*       out  = (float*)d_out;           // [128, 1024]

    bp_fused<<<GRID, THREADS>>>(mask, x, out);   // single launch
}

// round 6
// speedup vs baseline: 1.0249x; 1.0249x over previous
#include <cuda_runtime.h>
#include <cuda_bf16.h>
#include <math.h>

#define BATCH   128
#define OUT_DIM 1024
#define IN_DIM  2048
#define MAXNNZ  64          // Poisson(8): P(row nnz > 64) ~ 1e-40 — safe cap
#define NSTRAIGHT 16        // unconditional gathers; sentinel-padded
#define GRID    128         // <= 148 SMs: ONE wave, co-residency guaranteed
#define THREADS 256

// Scratch (no allocations allowed anywhere):
__device__ int            g_cnt[OUT_DIM];
__device__ unsigned short g_idx[OUT_DIM][MAXNNZ];     // row-major, 128B rows
__device__ float          g_xT[(IN_DIM + 1) * BATCH]; // transposed x + sentinel row = 1.0f
__device__ unsigned long long g_bar;                  // monotonic barrier (replay-safe)

// Grid barrier: monotonic counter — each launch adds exactly GRID arrivals,
// target derived from observed generation, so no reset across graph replays.
__device__ __forceinline__ void grid_sync() {
    __syncthreads();
    if (threadIdx.x == 0) {
        __threadfence();                               // release phase-1 writes
        unsigned long long old = atomicAdd(&g_bar, 1ULL);
        unsigned long long target = (old / GRID + 1ULL) * GRID;
        while (*(volatile unsigned long long*)&g_bar < target)
            __nanosleep(32);
        __threadfence();                               // acquire peers' writes
    }
    __syncthreads();
}

__global__ void __launch_bounds__(THREADS, 1)          // min-blocks 1: no reg squeeze
bp_fused(const float* __restrict__ mask, const float* __restrict__ x,
         float* __restrict__ out) {
    __shared__ float smem[16 * 130];                   // 8320B, reused per phase
    const int tid  = threadIdx.x;
    const int lane = tid & 31;

    // ============ Phase 1a: index build — warp = one mask row ============
    {
        const int o = blockIdx.x * 8 + (tid >> 5);
        const float4* row4 =
            reinterpret_cast<const float4*>(mask + (size_t)o * IN_DIM);

        float4 v[16];                                  // whole 8KB row in flight
        #pragma unroll
        for (int u = 0; u < 16; u++) v[u] = row4[u * 32 + lane];

        int mycnt = 0;
        #pragma unroll
        for (int u = 0; u < 16; u++)
            mycnt += (v[u].x != 0.0f) + (v[u].y != 0.0f) +
                     (v[u].z != 0.0f) + (v[u].w != 0.0f);

        int scan = mycnt;                              // inclusive warp scan
        #pragma unroll
        for (int d = 1; d < 32; d <<= 1) {
            int t = __shfl_up_sync(0xffffffffu, scan, d);
            if (lane >= d) scan += t;
        }
        int total = __shfl_sync(0xffffffffu, scan, 31);
        int pos   = scan - mycnt;                      // order-free is fine

        #pragma unroll
        for (int u = 0; u < 16; u++) {
            float m[4] = {v[u].x, v[u].y, v[u].z, v[u].w};
            #pragma unroll
            for (int k = 0; k < 4; k++) {
                if (m[k] != 0.0f) {
                    if (pos < MAXNNZ)
                        g_idx[o][pos] = (unsigned short)((u * 32 + lane) * 4 + k);
                    pos++;
                }
            }
        }
        for (int j = total + lane; j < NSTRAIGHT; j += 32)  // sentinel pad
            g_idx[o][j] = (unsigned short)IN_DIM;
        if (lane == 0) g_cnt[o] = total < MAXNNZ ? total : MAXNNZ;
    }
    __syncthreads();

    // ============ Phase 1b: transpose one 16-column strip of x ============
    {
        const int c0 = blockIdx.x * 16;                // 128 blocks x 16 = 2048
        const int c  = tid & 15;
        const int br = tid >> 4;                       // 0..15
        #pragma unroll
        for (int it = 0; it < 8; it++) {               // 128 batches
            const int b = br + 16 * it;
            smem[c * 130 + b] = x[(size_t)b * IN_DIM + c0 + c];
        }
        __syncthreads();
        const int b2 = tid & 127;
        const int cc = tid >> 7;                       // 0..1
        #pragma unroll
        for (int it = 0; it < 8; it++) {               // 16 cols, 2 per pass
            const int c3 = cc + 2 * it;
            g_xT[(size_t)(c0 + c3) * BATCH + b2] = smem[c3 * 130 + b2];
        }
        if (blockIdx.x == 0 && tid < BATCH)            // sentinel row -> 1.0f
            g_xT[(size_t)IN_DIM * BATCH + tid] = 1.0f;
    }

    // ========================== grid barrier ==========================
    grid_sync();

    // ============ Phase 2: check-node update (R4 logic) ============
    // Tile = 32 check nodes x 32 batches; warp handles 4 o's x 32 lanes.
    // Indices warp-uniform (broadcast); 64 coalesced gathers in flight.
    float* s_t = smem;                                 // [32][33] view
    {
        const int o0 = (blockIdx.x >> 2) * 32;
        const int b0 = (blockIdx.x & 3) * 32;
        const int w  = tid >> 5;

        #pragma unroll
        for (int q = 0; q < 4; q++) {
            const int ol = w * 4 + q;                  // local o: 0..31
            const int o  = o0 + ol;

            const uint4* gi = reinterpret_cast<const uint4*>(&g_idx[o][0]);
            const uint4 A = gi[0], B = gi[1];          // uniform -> broadcast
            const int   n = g_cnt[o];

            int id[NSTRAIGHT];
            {
                const unsigned wd[8] = {A.x, A.y, A.z, A.w, B.x, B.y, B.z, B.w};
                #pragma unroll
                for (int k = 0; k < 8; k++) {
                    id[2 * k]     = wd[k] & 0xffffu;
                    id[2 * k + 1] = wd[k] >> 16;
                }
            }

            float v[NSTRAIGHT];
            #pragma unroll
            for (int k = 0; k < NSTRAIGHT; k++)
                v[k] = g_xT[(size_t)id[k] * BATCH + b0 + lane];

            float p = (((v[0]  * v[1])  * (v[2]  * v[3])) *
                       ((v[4]  * v[5])  * (v[6]  * v[7]))) *
                      (((v[8]  * v[9])  * (v[10] * v[11])) *
                       ((v[12] * v[13]) * (v[14] * v[15])));

            #pragma unroll 1
            for (int j = NSTRAIGHT; j < n; j++)        // warp-uniform, rare
                p *= g_xT[(size_t)g_idx[o][j] * BATCH + b0 + lane];

            const float lim = 1.0f - 1e-7f;            // folds to 0.99999988f
            p = fminf(fmaxf(p, -lim), lim);
            s_t[ol * 33 + lane] = __logf((1.0f + p) / (1.0f - p));
        }
        __syncthreads();

        #pragma unroll
        for (int e = 0; e < 4; e++) {                  // coalesced stores
            const int idx = tid + e * 256;
            const int r = idx >> 5;                    // batch local
            const int c = idx & 31;                    // o local
            out[(size_t)(b0 + r) * OUT_DIM + o0 + c] = s_t[c * 33 + r];
        }
    }
}

// ---------------------------------------------------------------------------
extern "C" void kernel_launch(void* const* d_in, const int* in_sizes, int n_in,
                              void* d_out, int out_size) {
    const float* x    = (const float*)d_in[0];   // [128, 2048]
    const float* mask = (const float*)d_in[1];   // [1024, 2048]
    float*       out  = (float*)d_out;           // [128, 1024]

    bp_fused<<<GRID, THREADS>>>(mask, x, out);   // single launch, single wave
}

// round 7
// speedup vs baseline: 1.2232x; 1.1935x over previous
#include <cuda_runtime.h>
#include <cuda_bf16.h>
#include <math.h>

#define BATCH   128
#define OUT_DIM 1024
#define IN_DIM  2048
#define MAXNNZ  64          // Poisson(8): P(row nnz > 64) ~ 1e-40 — safe cap
#define NSTRAIGHT 16        // unconditional gathers; sentinel-padded

// Scratch (no allocations allowed anywhere):
__device__ int            g_cnt[OUT_DIM];
__device__ unsigned short g_idx[OUT_DIM][MAXNNZ];     // row-major, 128B rows
__device__ float          g_xT[(IN_DIM + 1) * BATCH]; // transposed x + sentinel row = 1.0f

// ---------------------------------------------------------------------------
// Kernel 1 (fused by blockIdx; 192 blocks x 256 threads):
//   blocks [0,128):   index build — warp = one mask row, BITMASK compaction.
//     Each float4 load collapses instantly to 4 predicate bits -> no long
//     live ranges -> no spills -> full MLP on the 8MB mask read.
//   blocks [128,192): x transpose (32-column strip, classic tile transpose).
// ---------------------------------------------------------------------------
__global__ void __launch_bounds__(256)
build_and_transpose(const float* __restrict__ mask, const float* __restrict__ x) {
    const int tid  = threadIdx.x;
    const int lane = tid & 31;

    if (blockIdx.x < 128) {
        const int o = blockIdx.x * 8 + (tid >> 5);
        const float4* row4 =
            reinterpret_cast<const float4*>(mask + (size_t)o * IN_DIM);

        // Per-lane 64-bit nonzero mask: bit (u*4+k) = row4[u*32+lane] comp k.
        unsigned long long m = 0;
        #pragma unroll
        for (int half = 0; half < 2; half++) {
            float4 v[8];                                // 8 x 16B in flight
            #pragma unroll
            for (int u = 0; u < 8; u++)
                v[u] = row4[(half * 8 + u) * 32 + lane];
            #pragma unroll
            for (int u = 0; u < 8; u++) {
                unsigned bits = (unsigned)(v[u].x != 0.0f)
                              | ((unsigned)(v[u].y != 0.0f) << 1)
                              | ((unsigned)(v[u].z != 0.0f) << 2)
                              | ((unsigned)(v[u].w != 0.0f) << 3);
                m |= (unsigned long long)bits << ((half * 8 + u) * 4);
            }
        }

        int mycnt = __popcll(m);
        int scan  = mycnt;                              // inclusive warp scan
        #pragma unroll
        for (int d = 1; d < 32; d <<= 1) {
            int t = __shfl_up_sync(0xffffffffu, scan, d);
            if (lane >= d) scan += t;
        }
        const int total = __shfl_sync(0xffffffffu, scan, 31);
        int pos = scan - mycnt;                         // exclusive prefix

        // Scatter set bits (order-free: downstream product is commutative)
        while (m) {
            int bit = __ffsll((long long)m) - 1;
            m &= m - 1;
            int col = ((bit >> 2) * 32 + lane) * 4 + (bit & 3);
            if (pos < MAXNNZ)
                g_idx[o][pos] = (unsigned short)col;
            pos++;
        }
        for (int j = total + lane; j < NSTRAIGHT; j += 32)   // sentinel pad
            g_idx[o][j] = (unsigned short)IN_DIM;
        if (lane == 0) g_cnt[o] = total < MAXNNZ ? total : MAXNNZ;

    } else {
        // ---- transpose strip: 32 columns x 128 batches ----
        __shared__ float tile[32][33];
        const int c0 = (blockIdx.x - 128) * 32;
        const int tx = lane;
        const int ty = tid >> 5;                        // 0..7
        #pragma unroll
        for (int bt = 0; bt < 4; bt++) {
            const int b0 = bt * 32;
            #pragma unroll
            for (int i = 0; i < 4; i++)
                tile[ty + 8 * i][tx] =
                    x[(size_t)(b0 + ty + 8 * i) * IN_DIM + c0 + tx];
            __syncthreads();
            #pragma unroll
            for (int i = 0; i < 4; i++)
                g_xT[(size_t)(c0 + ty + 8 * i) * BATCH + b0 + tx] =
                    tile[tx][ty + 8 * i];
            __syncthreads();
        }
        if (blockIdx.x == 128 && tid < BATCH)           // sentinel row -> 1.0f
            g_xT[(size_t)IN_DIM * BATCH + tid] = 1.0f;
    }
}

// ---------------------------------------------------------------------------
// Kernel 2: tile = 16 check nodes x 32 batches, 512 threads, 256 blocks
// (finer blocks: ~3.5 half-size blocks per SM -> better balance + latency
// hiding). Warp w owns o = o0+w for all lanes: indices warp-uniform
// (broadcast); 16 fully-coalesced 128B gathers from L2-resident g_xT.
// ---------------------------------------------------------------------------
__global__ void __launch_bounds__(512)
check_node_update(float* __restrict__ out) {
    __shared__ float s_t[16][33];

    const int tx = threadIdx.x & 31;            // batch lane
    const int w  = threadIdx.x >> 5;            // 0..15: check node in tile
    const int o0 = blockIdx.x * 16;
    const int o  = o0 + w;
    const int b0 = blockIdx.y * 32;

    const uint4* gi = reinterpret_cast<const uint4*>(&g_idx[o][0]);
    const uint4 A = gi[0], B = gi[1];           // uniform -> broadcast
    const int   n = g_cnt[o];

    int id[NSTRAIGHT];
    {
        const unsigned wd[8] = {A.x, A.y, A.z, A.w, B.x, B.y, B.z, B.w};
        #pragma unroll
        for (int k = 0; k < 8; k++) {
            id[2 * k]     = wd[k] & 0xffffu;
            id[2 * k + 1] = wd[k] >> 16;
        }
    }

    const float* __restrict__ xb = g_xT + b0 + tx;
    float v[NSTRAIGHT];
    #pragma unroll
    for (int k = 0; k < NSTRAIGHT; k++)         // 16 independent gathers
        v[k] = xb[(size_t)id[k] * BATCH];

    float p = (((v[0]  * v[1])  * (v[2]  * v[3])) *
               ((v[4]  * v[5])  * (v[6]  * v[7]))) *
              (((v[8]  * v[9])  * (v[10] * v[11])) *
               ((v[12] * v[13]) * (v[14] * v[15])));

    #pragma unroll 1
    for (int j = NSTRAIGHT; j < n; j++)          // warp-uniform, ~0.4% of rows
        p *= xb[(size_t)g_idx[o][j] * BATCH];

    const float lim = 1.0f - 1e-7f;              // folds to 0.99999988f
    p = fminf(fmaxf(p, -lim), lim);

    s_t[w][tx] = __logf((1.0f + p) / (1.0f - p));
    __syncthreads();

    // 512 elements: thread -> (b local r, o local c); 64B segments per store
    const int r = threadIdx.x >> 4;              // 0..31
    const int c = threadIdx.x & 15;              // 0..15
    out[(size_t)(b0 + r) * OUT_DIM + o0 + c] = s_t[c][r];
}

// ---------------------------------------------------------------------------
extern "C" void kernel_launch(void* const* d_in, const int* in_sizes, int n_in,
                              void* d_out, int out_size) {
    const float* x    = (const float*)d_in[0];   // [128, 2048]
    const float* mask = (const float*)d_in[1];   // [1024, 2048]
    float*       out  = (float*)d_out;           // [128, 1024]

    build_and_transpose<<<192, 256>>>(mask, x);  // 128 build + 64 transpose

    dim3 grd(OUT_DIM / 16, BATCH / 32);          // (64, 4) = 256 blocks
    check_node_update<<<grd, 512>>>(out);
}